// round 3
// baseline (speedup 1.0000x reference)
#include <cuda_runtime.h>

// FeedForwardAttention — algebraically reduced, softmax normalization deferred.
// attns[b,q,k] = softmax_k(fk[b,k]),  fk[b,l] = (Wk^T fck_w) . key[b,l]
// out[b,q,:] = (1/sum_k e[b,k]) * Wv @ (sum_k e[b,k] value[b,k,:]) + bv
// where e = exp(fk) unnormalized (|fk| ~ 0.3, no max-subtraction needed).
// HBM floor: read key 64MB + value 64MB, write out 64MB ≈ 26us.

#define BB 8
#define LL 2048
#define CC 1024
#define NROWS (BB * LL)          // 16384
#define NCHUNK 128
#define KCHUNK (LL / NCHUNK)     // 16
#define UOC 64                   // o-chunks for u partials (16 rows each)

__device__ float g_upart[UOC * CC];
__device__ float g_u[CC];
__device__ float g_p[NROWS];                   // unnormalized exp(fk)
__device__ float g_esp[NROWS / 8];             // per-block partial e-sums (2048)
__device__ float g_esum[BB];
__device__ float g_part[NCHUNK * BB * CC];     // 4MB partial weighted value sums
__device__ float g_vbar[BB * CC];
__device__ float g_outs[BB * CC];

// ---- kernel 0a: partial u: block (cx, oc) sums 16 o-rows for 256 c ---------
__global__ void k_u_part(const float* __restrict__ Wk, const float* __restrict__ fckw) {
    int c  = blockIdx.x * 256 + threadIdx.x;
    int oc = blockIdx.y;                              // 64 chunks of 16 rows
    int o0 = oc * (CC / UOC);
    float acc = 0.f;
#pragma unroll
    for (int o = 0; o < CC / UOC; ++o)
        acc += fckw[o0 + o] * Wk[(size_t)(o0 + o) * CC + c];
    g_upart[oc * CC + c] = acc;
}

// ---- kernel 0b: reduce 64 partials -----------------------------------------
__global__ void k_u_reduce() {
    int c = blockIdx.x * 256 + threadIdx.x;
    float acc = 0.f;
#pragma unroll
    for (int oc = 0; oc < UOC; ++oc) acc += g_upart[oc * CC + c];
    g_u[c] = acc;
}

// ---- kernel 1: e[row] = exp(u . key[row]) + per-block partial sums ---------
__global__ void k_fk(const float* __restrict__ key) {
    __shared__ float se[8];
    int warp = threadIdx.x >> 5, lane = threadIdx.x & 31;
    int row = blockIdx.x * 8 + warp;                  // 8 rows, same batch
    const float4* kp = (const float4*)(key + (size_t)row * CC);
    const float4* up = (const float4*)g_u;
    float acc = 0.f;
#pragma unroll
    for (int i = 0; i < 8; ++i) {
        int idx = lane + i * 32;                      // 256 float4 per row
        float4 kv = kp[idx];
        float4 uv = up[idx];
        acc += kv.x * uv.x + kv.y * uv.y + kv.z * uv.z + kv.w * uv.w;
    }
#pragma unroll
    for (int o = 16; o; o >>= 1) acc += __shfl_xor_sync(0xFFFFFFFFu, acc, o);
    float e = __expf(acc);
    if (lane == 0) { g_p[row] = e; se[warp] = e; }
    __syncthreads();
    if (threadIdx.x == 0) {
        float s = 0.f;
#pragma unroll
        for (int w = 0; w < 8; ++w) s += se[w];
        g_esp[blockIdx.x] = s;                        // batch = blockIdx.x / 256
    }
}

// ---- kernel 2: per-batch e-sum (8 blocks x 256 partials) -------------------
__global__ void k_esum() {
    __shared__ float red[8];
    int b = blockIdx.x, t = threadIdx.x, lane = t & 31, warp = t >> 5;
    float v = g_esp[b * 256 + t];
#pragma unroll
    for (int o = 16; o; o >>= 1) v += __shfl_xor_sync(0xFFFFFFFFu, v, o);
    if (lane == 0) red[warp] = v;
    __syncthreads();
    if (t == 0) {
        float s = 0.f;
#pragma unroll
        for (int w = 0; w < 8; ++w) s += red[w];
        g_esum[b] = s;
    }
}

// ---- kernel 3: partial v̄: block = (chunk of 16 k-rows, batch b) ------------
__global__ void k_vbar_part(const float* __restrict__ value) {
    int chunk = blockIdx.x, b = blockIdx.y, t = threadIdx.x;   // t: float4 slot
    __shared__ float sp[KCHUNK];
    int k0 = chunk * KCHUNK;
    if (t < KCHUNK) sp[t] = g_p[b * LL + k0 + t];
    __syncthreads();
    const float4* vp = (const float4*)(value + (size_t)(b * LL + k0) * CC);
    float4 acc = make_float4(0.f, 0.f, 0.f, 0.f);
#pragma unroll
    for (int k = 0; k < KCHUNK; ++k) {
        float p = sp[k];
        float4 v = vp[(size_t)k * (CC / 4) + t];
        acc.x += p * v.x; acc.y += p * v.y; acc.z += p * v.z; acc.w += p * v.w;
    }
    ((float4*)g_part)[(size_t)(chunk * BB + b) * (CC / 4) + t] = acc;
}

// ---- kernel 4: deterministic partial reduce (float4) -----------------------
__global__ void k_vbar_reduce() {
    int i = blockIdx.x * 256 + threadIdx.x;           // 0..2047 float4 slots
    const float4* pp = (const float4*)g_part;
    float4 acc = make_float4(0.f, 0.f, 0.f, 0.f);
#pragma unroll
    for (int ch = 0; ch < NCHUNK; ++ch) {
        float4 v = pp[(size_t)ch * (BB * CC / 4) + i];
        acc.x += v.x; acc.y += v.y; acc.z += v.z; acc.w += v.w;
    }
    ((float4*)g_vbar)[i] = acc;
}

// ---- kernel 5: outs[b,d] = (Wv[d,:] . vbar[b,:]) / esum[b] + bv[d] ---------
__global__ void k_out(const float* __restrict__ Wv, const float* __restrict__ bv) {
    int warp = threadIdx.x >> 5, lane = threadIdx.x & 31;
    int d = blockIdx.x * 8 + warp;
    const float4* wp = (const float4*)(Wv + (size_t)d * CC);
    const float4* vb = (const float4*)g_vbar;
    float acc[BB];
#pragma unroll
    for (int b = 0; b < BB; ++b) acc[b] = 0.f;
#pragma unroll
    for (int i = 0; i < 8; ++i) {
        int idx = lane + i * 32;
        float4 w = wp[idx];
#pragma unroll
        for (int b = 0; b < BB; ++b) {
            float4 v = vb[b * (CC / 4) + idx];
            acc[b] += w.x * v.x + w.y * v.y + w.z * v.z + w.w * v.w;
        }
    }
#pragma unroll
    for (int b = 0; b < BB; ++b)
#pragma unroll
        for (int o = 16; o; o >>= 1) acc[b] += __shfl_xor_sync(0xFFFFFFFFu, acc[b], o);
    if (lane == 0) {
        float bias = bv[d];
#pragma unroll
        for (int b = 0; b < BB; ++b)
            g_outs[b * CC + d] = acc[b] * (1.f / g_esum[b]) + bias;
    }
}

// ---- kernel 6: broadcast outs[b,:] to all 2048 q rows ----------------------
__global__ void k_bcast(float4* __restrict__ out) {
    int i = blockIdx.x * blockDim.x + threadIdx.x;   // float4 index
    int b  = i >> 19;                                // 524288 float4 per batch
    int d4 = i & 255;                                // 256 float4 per out row
    out[i] = ((const float4*)g_outs)[b * 256 + d4];
}

extern "C" void kernel_launch(void* const* d_in, const int* in_sizes, int n_in,
                              void* d_out, int out_size) {
    const float* key   = (const float*)d_in[1];
    const float* value = (const float*)d_in[2];
    const float* Wk    = (const float*)d_in[5];
    const float* Wv    = (const float*)d_in[7];
    const float* bv    = (const float*)d_in[8];
    const float* fckw  = (const float*)d_in[11];

    dim3 gu(CC / 256, UOC);
    k_u_part<<<gu, 256>>>(Wk, fckw);
    k_u_reduce<<<CC / 256, 256>>>();
    k_fk<<<NROWS / 8, 256>>>(key);
    k_esum<<<BB, 256>>>();
    dim3 gpart(NCHUNK, BB);
    k_vbar_part<<<gpart, 256>>>(value);
    k_vbar_reduce<<<(BB * CC / 4) / 256, 256>>>();
    k_out<<<CC / 8, 256>>>(Wv, bv);
    k_bcast<<<(BB * LL * CC / 4) / 256, 256>>>((float4*)d_out);
}

// round 4
// speedup vs baseline: 1.1236x; 1.1236x over previous
#include <cuda_runtime.h>

// FeedForwardAttention — algebraically reduced, single persistent kernel.
//   attns[b,q,:] = softmax_k(u . key[b,k]),  u = Wk^T fck_w   (fq, bq, bk, fck_b cancel)
//   out[b,q,:]   = Wv @ (sum_k e_k value[b,k,:]) / (sum_k e_k) + bv   (q-independent)
// One launch; phases separated by a software grid barrier (generation counter).
// HBM: read key+value 128MB fused pass, write out 64MB. Floor ~ 27us.

#define BB 8
#define LL 2048
#define CC 1024
#define GRID 148
#define TPB 1024

#define P0B 128            // u-partial blocks, 8 o-rows each
#define P1B 128            // fused-pass blocks: 16 per batch
#define BPB 16             // blocks per batch
#define RPB 128            // rows per block (P1)
#define GRP 4              // groups of 32 rows

__device__ float g_upart[P0B * CC];            // 512KB
__device__ float g_u[CC];
__device__ float g_vpart[P1B * 4 * CC];        // 2MB: [blk][quarter][c]
__device__ float g_eblk[P1B];
__device__ float g_vbar[BB * CC];              // scaled by 1/esum
__device__ float g_outs[BB * CC];
__device__ unsigned g_count = 0;
__device__ unsigned g_gen = 0;

__device__ __forceinline__ void grid_barrier() {
    __syncthreads();
    if (threadIdx.x == 0) {
        unsigned gen = *(volatile unsigned*)&g_gen;
        __threadfence();
        if (atomicAdd(&g_count, 1u) == GRID - 1) {
            atomicExch(&g_count, 0u);
            __threadfence();
            atomicAdd(&g_gen, 1u);
        } else {
            while (*(volatile unsigned*)&g_gen == gen) __nanosleep(32);
            __threadfence();
        }
    }
    __syncthreads();
}

__global__ void __launch_bounds__(TPB, 1) k_fused(
    const float* __restrict__ key, const float* __restrict__ value,
    const float* __restrict__ Wk, const float* __restrict__ Wv,
    const float* __restrict__ bv, const float* __restrict__ fckw,
    float4* __restrict__ out)
{
    __shared__ float4 su4[CC / 4];
    __shared__ float se[32];
    __shared__ float sew[32];
    __shared__ float s_scale;

    const int bk = blockIdx.x, t = threadIdx.x;
    const int w = t >> 5, lane = t & 31;

    // ---- P0: u partials. block bk<128 sums 8 o-rows for all 1024 c --------
    if (bk < P0B) {
        int o0 = bk * 8;
        float acc = 0.f;
#pragma unroll
        for (int o = 0; o < 8; ++o)
            acc += fckw[o0 + o] * Wk[(size_t)(o0 + o) * CC + t];
        g_upart[bk * CC + t] = acc;
    }
    grid_barrier();

    // ---- P0b: u reduce (block 0) ------------------------------------------
    if (bk == 0) {
        float acc = 0.f;
#pragma unroll
        for (int j = 0; j < P0B; ++j) acc += g_upart[j * CC + t];
        g_u[t] = acc;
    }
    grid_barrier();

    // ---- P1: fused e = exp(u.key) and vpart += e*value (128 blocks) -------
    if (bk < P1B) {
        // stage u into smem
        if (t < CC / 4) su4[t] = ((const float4*)g_u)[t];
        __syncthreads();
        int b = bk / BPB;
        int row0 = b * LL + (bk % BPB) * RPB;
        int q = t >> 8;            // 0..3: which 8-row slice of each 32-group
        int c4 = t & 255;          // float4 column
        float4 acc = make_float4(0.f, 0.f, 0.f, 0.f);
        float e_acc = 0.f;
        const float4* kp = (const float4*)key;
        const float4* vp = (const float4*)value;
#pragma unroll
        for (int g = 0; g < GRP; ++g) {
            // 32 warps each dot one row with u
            int row = row0 + g * 32 + w;
            const float4* kr = kp + (size_t)row * 256;
            float d = 0.f;
#pragma unroll
            for (int i = 0; i < 8; ++i) {
                float4 kv = kr[lane + i * 32];
                float4 uv = su4[lane + i * 32];
                d += kv.x * uv.x + kv.y * uv.y + kv.z * uv.z + kv.w * uv.w;
            }
#pragma unroll
            for (int o = 16; o; o >>= 1) d += __shfl_xor_sync(0xFFFFFFFFu, d, o);
            float e = __expf(d);
            if (lane == 0) { se[w] = e; e_acc += e; }
            __syncthreads();
            // each quarter accumulates its 8 rows at its 256 float4 columns
            int rg0 = row0 + g * 32 + q * 8;
#pragma unroll
            for (int r = 0; r < 8; ++r) {
                float p = se[q * 8 + r];
                float4 v = vp[(size_t)(rg0 + r) * 256 + c4];
                acc.x += p * v.x; acc.y += p * v.y; acc.z += p * v.z; acc.w += p * v.w;
            }
            __syncthreads();
        }
        ((float4*)g_vpart)[(size_t)(bk * 4 + q) * 256 + c4] = acc;
        if (lane == 0) sew[w] = e_acc;
        __syncthreads();
        if (t == 0) {
            float s = 0.f;
#pragma unroll
            for (int j = 0; j < 32; ++j) s += sew[j];
            g_eblk[bk] = s;
        }
    }
    grid_barrier();

    // ---- P2: vbar[b][c] = (sum over 16 blk x 4 q partials) / esum[b] ------
    if (bk < BB) {
        if (t == 0) {
            float es = 0.f;
#pragma unroll
            for (int j = 0; j < BPB; ++j) es += g_eblk[bk * BPB + j];
            s_scale = 1.f / es;
        }
        float acc = 0.f;
#pragma unroll
        for (int j = 0; j < BPB; ++j)
#pragma unroll
            for (int qq = 0; qq < 4; ++qq)
                acc += g_vpart[(size_t)((bk * BPB + j) * 4 + qq) * CC + t];
        __syncthreads();
        g_vbar[bk * CC + t] = acc * s_scale;
    }
    grid_barrier();

    // ---- P3: outs[b][d] = Wv[d] . vbar[b] + bv[d]  (blocks 0..31) ---------
    if (bk < 32) {
        int d = bk * 32 + w;
        const float4* wp = (const float4*)(Wv + (size_t)d * CC);
        const float4* vb = (const float4*)g_vbar;
        float acc[BB];
#pragma unroll
        for (int b = 0; b < BB; ++b) acc[b] = 0.f;
#pragma unroll
        for (int i = 0; i < 8; ++i) {
            int idx = lane + i * 32;
            float4 wv = wp[idx];
#pragma unroll
            for (int b = 0; b < BB; ++b) {
                float4 v = vb[b * 256 + idx];
                acc[b] += wv.x * v.x + wv.y * v.y + wv.z * v.z + wv.w * v.w;
            }
        }
#pragma unroll
        for (int b = 0; b < BB; ++b)
#pragma unroll
            for (int o = 16; o; o >>= 1)
                acc[b] += __shfl_xor_sync(0xFFFFFFFFu, acc[b], o);
        if (lane == 0) {
            float bias = bv[d];
#pragma unroll
            for (int b = 0; b < BB; ++b) g_outs[b * CC + d] = acc[b] + bias;
        }
    }
    grid_barrier();

    // ---- P4: broadcast outs[b,:] to all q rows (64MB write) ---------------
    {
        const float4* os = (const float4*)g_outs;
        const int total4 = BB * LL * CC / 4;        // 4,194,304
        for (int i = bk * TPB + t; i < total4; i += GRID * TPB) {
            int b  = i >> 19;
            int d4 = i & 255;
            out[i] = os[b * 256 + d4];
        }
    }
}

extern "C" void kernel_launch(void* const* d_in, const int* in_sizes, int n_in,
                              void* d_out, int out_size) {
    const float* key   = (const float*)d_in[1];
    const float* value = (const float*)d_in[2];
    const float* Wk    = (const float*)d_in[5];
    const float* Wv    = (const float*)d_in[7];
    const float* bv    = (const float*)d_in[8];
    const float* fckw  = (const float*)d_in[11];
    k_fused<<<GRID, TPB>>>(key, value, Wk, Wv, bv, fckw, (float4*)d_out);
}

// round 5
// speedup vs baseline: 1.1648x; 1.0367x over previous
#include <cuda_runtime.h>

// FeedForwardAttention — algebraically reduced, single persistent kernel.
//   attns[b,q,:] = softmax_k(u . key[b,k]),  u = Wk^T fck_w
//   out[b,q,:]   = Wv @ (sum_k e_k value[b,k,:]) / (sum_k e_k) + bv  (q-independent)
// Phases: P0 u-partials | P0b u-reduce | P1 fused e+value (sync-minimal) |
//         P2 vbar reduce | P3 Wv GEMV | P4 broadcast write.  5 grid barriers.

#define BB 8
#define LL 2048
#define CC 1024
#define GRID 148
#define TPB 1024
#define P0B 128            // u-partial blocks, 8 o-rows each
#define P1B 128            // fused blocks: 16 per batch, 128 rows each

__device__ float g_upart[P0B * CC];
__device__ float g_u[CC];
__device__ float g_vpart[P1B * CC];            // 512KB block partials
__device__ float g_eblk[P1B];
__device__ float g_vbar[BB * CC];
__device__ float g_outs[BB * CC];
__device__ unsigned g_count = 0;
__device__ unsigned g_gen = 0;

__device__ __forceinline__ void grid_barrier() {
    __syncthreads();
    if (threadIdx.x == 0) {
        unsigned gen = *(volatile unsigned*)&g_gen;
        __threadfence();
        if (atomicAdd(&g_count, 1u) == GRID - 1) {
            atomicExch(&g_count, 0u);
            __threadfence();
            atomicAdd(&g_gen, 1u);
        } else {
            while (*(volatile unsigned*)&g_gen == gen) { }
            __threadfence();
        }
    }
    __syncthreads();
}

__global__ void __launch_bounds__(TPB, 1) k_fused(
    const float* __restrict__ key, const float* __restrict__ value,
    const float* __restrict__ Wk, const float* __restrict__ Wv,
    const float* __restrict__ bv, const float* __restrict__ fckw,
    float4* __restrict__ out)
{
    __shared__ float4 su4[CC / 4];      // staged u
    __shared__ float  se[128];          // per-row e within block
    __shared__ float4 sbuf[8][CC / 4];  // 32KB staged warp-partial reduce
    __shared__ float  s_scale;

    const int bk = blockIdx.x, t = threadIdx.x;
    const int w = t >> 5, lane = t & 31;

    // ---- P0: u partials --------------------------------------------------
    if (bk < P0B) {
        int o0 = bk * 8;
        float acc = 0.f;
#pragma unroll
        for (int o = 0; o < 8; ++o)
            acc += fckw[o0 + o] * Wk[(size_t)(o0 + o) * CC + t];
        g_upart[bk * CC + t] = acc;
    }
    grid_barrier();

    // ---- P0b: u reduce (block 0) -----------------------------------------
    if (bk == 0) {
        float acc = 0.f;
#pragma unroll
        for (int j = 0; j < P0B; ++j) acc += g_upart[j * CC + t];
        g_u[t] = acc;
    }
    grid_barrier();

    // ---- P1: fused e = exp(u.key) + vpart = sum e*value (128 blocks) -----
    if (bk < P1B) {
        if (t < CC / 4) su4[t] = ((const float4*)g_u)[t];
        __syncthreads();
        const int b = bk >> 4;
        const int row0 = b * LL + (bk & 15) * 128;

        // dot phase: warp w handles rows row0 + 32*it + w, it<4
#pragma unroll
        for (int it = 0; it < 4; ++it) {
            int row = row0 + it * 32 + w;
            const float4* kr = (const float4*)key + (size_t)row * 256;
            float d = 0.f;
#pragma unroll
            for (int i = 0; i < 8; ++i) {
                float4 kv = kr[lane + i * 32];
                float4 uv = su4[lane + i * 32];
                d += kv.x * uv.x + kv.y * uv.y + kv.z * uv.z + kv.w * uv.w;
            }
#pragma unroll
            for (int o = 16; o; o >>= 1) d += __shfl_xor_sync(0xFFFFFFFFu, d, o);
            if (lane == 0) se[it * 32 + w] = __expf(d);
        }
        __syncthreads();

        // value phase: same rows, no syncs in loop
        float4 acc[8];
#pragma unroll
        for (int i = 0; i < 8; ++i) acc[i] = make_float4(0.f, 0.f, 0.f, 0.f);
#pragma unroll
        for (int it = 0; it < 4; ++it) {
            int row = row0 + it * 32 + w;
            float e = se[it * 32 + w];
            const float4* vr = (const float4*)value + (size_t)row * 256;
#pragma unroll
            for (int i = 0; i < 8; ++i) {
                float4 v = vr[lane + i * 32];
                acc[i].x += e * v.x; acc[i].y += e * v.y;
                acc[i].z += e * v.z; acc[i].w += e * v.w;
            }
        }

        // staged reduce: 32 warp partials -> 8 bufs -> 1
        if (w < 8) {
#pragma unroll
            for (int i = 0; i < 8; ++i) sbuf[w][lane + i * 32] = acc[i];
        }
        __syncthreads();
#pragma unroll
        for (int stage = 1; stage < 4; ++stage) {
            if (w >= stage * 8 && w < stage * 8 + 8) {
                int bf = w - stage * 8;
#pragma unroll
                for (int i = 0; i < 8; ++i) {
                    float4 c = sbuf[bf][lane + i * 32];
                    c.x += acc[i].x; c.y += acc[i].y; c.z += acc[i].z; c.w += acc[i].w;
                    sbuf[bf][lane + i * 32] = c;
                }
            }
            __syncthreads();
        }
        if (t < 256) {
            float4 s = make_float4(0.f, 0.f, 0.f, 0.f);
#pragma unroll
            for (int j = 0; j < 8; ++j) {
                float4 c = sbuf[j][t];
                s.x += c.x; s.y += c.y; s.z += c.z; s.w += c.w;
            }
            ((float4*)g_vpart)[bk * 256 + t] = s;
        } else if (w == 8) {
            // e-block-sum: lane sums se[lane*4 .. +4], then warp reduce
            float s = se[lane * 4] + se[lane * 4 + 1] + se[lane * 4 + 2] + se[lane * 4 + 3];
#pragma unroll
            for (int o = 16; o; o >>= 1) s += __shfl_xor_sync(0xFFFFFFFFu, s, o);
            if (lane == 0) g_eblk[bk] = s;
        }
    }
    grid_barrier();

    // ---- P2: vbar[b][c] = sum_j vpart / esum[b]  (8 blocks) ---------------
    if (bk < BB) {
        if (t == 0) {
            float es = 0.f;
#pragma unroll
            for (int j = 0; j < 16; ++j) es += g_eblk[bk * 16 + j];
            s_scale = 1.f / es;
        }
        float acc = 0.f;
#pragma unroll
        for (int j = 0; j < 16; ++j)
            acc += g_vpart[(size_t)(bk * 16 + j) * CC + t];
        __syncthreads();
        g_vbar[bk * CC + t] = acc * s_scale;
    }
    grid_barrier();

    // ---- P3: outs[b][d] = Wv[d] . vbar[b] + bv[d]  (32 blocks) ------------
    if (bk < 32) {
        int d = bk * 32 + w;
        const float4* wp = (const float4*)(Wv + (size_t)d * CC);
        const float4* vb = (const float4*)g_vbar;
        float acc[BB];
#pragma unroll
        for (int b = 0; b < BB; ++b) acc[b] = 0.f;
#pragma unroll
        for (int i = 0; i < 8; ++i) {
            int idx = lane + i * 32;
            float4 wv = wp[idx];
#pragma unroll
            for (int b = 0; b < BB; ++b) {
                float4 v = vb[b * 256 + idx];
                acc[b] += wv.x * v.x + wv.y * v.y + wv.z * v.z + wv.w * v.w;
            }
        }
#pragma unroll
        for (int b = 0; b < BB; ++b)
#pragma unroll
            for (int o = 16; o; o >>= 1)
                acc[b] += __shfl_xor_sync(0xFFFFFFFFu, acc[b], o);
        if (lane == 0) {
            float bias = bv[d];
#pragma unroll
            for (int b = 0; b < BB; ++b) g_outs[b * CC + d] = acc[b] + bias;
        }
    }
    grid_barrier();

    // ---- P4: broadcast outs[b,:] to all q rows (64MB write) ---------------
    {
        const float4* os = (const float4*)g_outs;
        const int total4 = BB * LL * CC / 4;
        for (int i = bk * TPB + t; i < total4; i += GRID * TPB) {
            int b  = i >> 19;
            int d4 = i & 255;
            out[i] = os[b * 256 + d4];
        }
    }
}

extern "C" void kernel_launch(void* const* d_in, const int* in_sizes, int n_in,
                              void* d_out, int out_size) {
    const float* key   = (const float*)d_in[1];
    const float* value = (const float*)d_in[2];
    const float* Wk    = (const float*)d_in[5];
    const float* Wv    = (const float*)d_in[7];
    const float* bv    = (const float*)d_in[8];
    const float* fckw  = (const float*)d_in[11];
    k_fused<<<GRID, TPB>>>(key, value, Wk, Wv, bv, fckw, (float4*)d_out);
}